// round 8
// baseline (speedup 1.0000x reference)
#include <cuda_runtime.h>
#include <cuda.h>
#include <cuda_fp16.h>
#include <cstdint>

// ---------------- problem dims ----------------
#define NB 32
#define CIN 256
#define HH 56
#define WW 56
#define WP 58
#define IMG_ROWS (WP*WP)            // 3364
#define R_VALID (NB*IMG_ROWS)       // 107648 = 128*841
#define R_TOTAL 107904
#define M_PER_CTA 128
#define N_PER_CTA 128
#define NTILES (841*2)
#define BSTAGES 2

// ---------------- smem layout ----------------
// barriers in [16,128); bias at 1024; A chunks at 2048 (4 x 17408);
// B ring at 71680 (2 x 16384); epilogue overlays A region.
#define SM_AFULL(k)  (16 + (k)*8)
#define SM_AEMPTY(k) (48 + (k)*8)
#define SM_BFULL(s)  (80 + (s)*8)
#define SM_BEMPTY(s) (96 + (s)*8)
#define SM_BIAS      1024
#define SM_ACH(k)    (2048 + (k)*17408)      // 130 rows x 128B, padded to 17408
#define SM_BST(s)    (71680 + (s)*16384)
#define SM_EPI       2048
#define SMEM_BYTES   104448                  // 2 CTAs/SM
#define A_TX 16640u                          // 130*128
#define B_TX 16384u

// ---------------- device scratch ----------------
__device__ __align__(1024) __half g_a[(size_t)R_TOTAL * 256];     // 55.25 MB
__device__ __align__(1024) __half g_b[(size_t)9 * 256 * 256];     // 1.18 MB

// ---------------- PTX helpers (plain-sm_103-legal) ----------------
__device__ __forceinline__ uint32_t smem_u32(const void* p) {
    uint32_t a;
    asm("{ .reg .u64 t; cvta.to.shared.u64 t, %1; cvt.u32.u64 %0, t; }" : "=r"(a) : "l"(p));
    return a;
}
__device__ __forceinline__ bool elect_one() {
    uint32_t p;
    asm volatile("{ .reg .pred P; elect.sync _|P, 0xFFFFFFFF; selp.b32 %0, 1, 0, P; }" : "=r"(p));
    return p != 0;
}
__device__ __forceinline__ void mbar_init(uint32_t a, uint32_t cnt) {
    asm volatile("mbarrier.init.shared.b64 [%0], %1;" :: "r"(a), "r"(cnt) : "memory");
}
__device__ __forceinline__ void mbar_expect_tx(uint32_t a, uint32_t bytes) {
    asm volatile("mbarrier.arrive.expect_tx.shared.b64 _, [%0], %1;" :: "r"(a), "r"(bytes) : "memory");
}
__device__ __forceinline__ void mbar_arrive(uint32_t a) {
    asm volatile("mbarrier.arrive.shared.b64 _, [%0];" :: "r"(a) : "memory");
}
__device__ __forceinline__ void mbar_wait(uint32_t a, uint32_t phase) {
    asm volatile(
        "{\n\t.reg .pred P;\n\t"
        "W_%=:\n\t"
        "mbarrier.try_wait.parity.acquire.cta.shared::cta.b64 P, [%0], %1, 0x989680;\n\t"
        "@P bra.uni D_%=;\n\t"
        "bra.uni W_%=;\n\t"
        "D_%=:\n\t}"
        :: "r"(a), "r"(phase) : "memory");
}
__device__ __forceinline__ void mbar_wait_relaxed(uint32_t a, uint32_t phase) {
    asm volatile(
        "{\n\t.reg .pred P;\n\t"
        "W_%=:\n\t"
        "mbarrier.try_wait.parity.relaxed.cta.shared::cta.b64 P, [%0], %1, 0x989680;\n\t"
        "@P bra.uni D_%=;\n\t"
        "bra.uni W_%=;\n\t"
        "D_%=:\n\t}"
        :: "r"(a), "r"(phase) : "memory");
}
__device__ __forceinline__ void tma2d(uint32_t dst, const CUtensorMap* m, int cx, int cy, uint32_t mbar) {
    asm volatile(
        "cp.async.bulk.tensor.2d.shared::cta.global.tile.mbarrier::complete_tx::bytes "
        "[%0], [%1, {%2, %3}], [%4];"
        :: "r"(dst), "l"(m), "r"(cx), "r"(cy), "r"(mbar) : "memory");
}
#define LDSM4(r0,r1,r2,r3,addr) \
    asm volatile("ldmatrix.sync.aligned.m8n8.x4.shared.b16 {%0,%1,%2,%3}, [%4];" \
        : "=r"(r0), "=r"(r1), "=r"(r2), "=r"(r3) : "r"(addr))
__device__ __forceinline__ void mma16816(float* c, const uint32_t* a, const uint32_t* b) {
    asm volatile(
        "mma.sync.aligned.m16n8k16.row.col.f32.f16.f16.f32 "
        "{%0,%1,%2,%3}, {%4,%5,%6,%7}, {%8,%9}, {%0,%1,%2,%3};"
        : "+f"(c[0]), "+f"(c[1]), "+f"(c[2]), "+f"(c[3])
        : "r"(a[0]), "r"(a[1]), "r"(a[2]), "r"(a[3]), "r"(b[0]), "r"(b[1]));
}

// ---------------- merged pre-pass: fill + border-zero + wprep ----------------
// blocks [0,7168): NCHW fp32 -> padded fp16 transpose
// blocks [7168,8112): zero border/tail rows
// blocks [8112,8368): sign(w) -> fp16 B[tap][co][ci]
#define FILL_BLKS (56*4*32)        // 7168
#define ZERO_BLKS 944
__global__ void k_pre(const float* __restrict__ x, const float* __restrict__ w) {
    __shared__ float s[64][57];
    int b = blockIdx.x;
    if (b < FILL_BLKS) {
        int n = b / 224, r = b % 224, cb = r / 56, h = r % 56;
        int ci0 = cb * 64;
        for (int idx = threadIdx.x; idx < 64 * 14; idx += blockDim.x) {
            int cl = idx / 14, q = idx % 14;
            float4 v = reinterpret_cast<const float4*>(
                x + (((size_t)n * CIN + ci0 + cl) * HH + h) * WW)[q];
            s[cl][q * 4 + 0] = v.x; s[cl][q * 4 + 1] = v.y;
            s[cl][q * 4 + 2] = v.z; s[cl][q * 4 + 3] = v.w;
        }
        __syncthreads();
        for (int idx = threadIdx.x; idx < WW * 32; idx += blockDim.x) {
            int ww = idx >> 5, p = idx & 31;
            __half2 hv = __floats2half2_rn(s[p * 2][ww], s[p * 2 + 1][ww]);
            size_t row = (size_t)n * IMG_ROWS + (size_t)(h + 1) * WP + (ww + 1);
            reinterpret_cast<__half2*>(g_a + row * 256 + ci0)[p] = hv;
        }
    } else if (b < FILL_BLKS + ZERO_BLKS) {
        int r = (b - FILL_BLKS) * 8 + (threadIdx.x >> 5);
        int lane = threadIdx.x & 31;
        size_t row;
        if (r < 32 * 228) {
            int n = r / 228, bb = r - n * 228;
            int y, xx;
            if (bb < 58)       { y = 0;  xx = bb; }
            else if (bb < 116) { y = 57; xx = bb - 58; }
            else if (bb < 172) { y = bb - 116 + 1; xx = 0; }
            else               { y = bb - 172 + 1; xx = 57; }
            row = (size_t)n * IMG_ROWS + (size_t)y * WP + xx;
        } else {
            row = (size_t)R_VALID + (r - 32 * 228);
        }
        uint4 z = make_uint4(0u, 0u, 0u, 0u);
        reinterpret_cast<uint4*>(g_a + row * 256)[lane] = z;
    } else {
        int t = (b - FILL_BLKS - ZERO_BLKS) * 256 + threadIdx.x;
        int co = t >> 8, ci = t & 255;
        const float* wp = w + (size_t)(co * 256 + ci) * 9;
        #pragma unroll
        for (int tap = 0; tap < 9; tap++) {
            float v = wp[tap];
            float sgn = (v > 0.f) ? 1.f : ((v < 0.f) ? -1.f : 0.f);
            g_b[((size_t)tap * 256 + co) * 256 + ci] = __float2half_rn(sgn);
        }
    }
}

// ---------------- main GEMM: 128m x 128n per CTA, A reused across kw ----------------
__global__ void __launch_bounds__(160, 2) k_gemm(
    const __grid_constant__ CUtensorMap tmA,
    const __grid_constant__ CUtensorMap tmB,
    const float* __restrict__ bias,
    float* __restrict__ out)
{
    extern __shared__ __align__(1024) char smem[];
    uint32_t sb = smem_u32(smem);
    int tid = threadIdx.x, wid = tid >> 5, lane = tid & 31;

    if (tid == 0) {
        #pragma unroll
        for (int k = 0; k < 4; k++) {
            mbar_init(sb + SM_AFULL(k), 1);
            mbar_init(sb + SM_AEMPTY(k), 4);
        }
        #pragma unroll
        for (int s = 0; s < BSTAGES; s++) {
            mbar_init(sb + SM_BFULL(s), 1);
            mbar_init(sb + SM_BEMPTY(s), 4);
        }
    }
    int mt  = blockIdx.x >> 1;
    int nco = blockIdx.x & 1;
    int tile_base = mt * M_PER_CTA;
    int co_base = nco * N_PER_CTA;

    float* sbias = reinterpret_cast<float*>(smem + SM_BIAS);
    if (tid < 128) sbias[tid] = bias[co_base + tid];
    __syncthreads();

    float acc[4][8][4];
    #pragma unroll
    for (int mi = 0; mi < 4; mi++)
        #pragma unroll
        for (int ni = 0; ni < 8; ni++)
            #pragma unroll
            for (int r = 0; r < 4; r++) acc[mi][ni][r] = 0.f;

    if (wid < 4) {
        // -------- compute warps: 2x2 grid, 64x64 warp tile --------
        int wr = wid >> 1, wc = wid & 1;
        uint32_t lm = lane & 15;
        uint32_t kbA = (lane >> 4) * 16;
        uint32_t co_off = (lane & 7) + ((lane >> 4) & 1) * 8;
        uint32_t kbB = ((lane >> 3) & 1) * 16;
        uint32_t xmB = (lane & 7) << 4;
        uint32_t xmk[3];
        #pragma unroll
        for (int kw = 0; kw < 3; kw++) xmk[kw] = ((lm + kw) & 7) << 4;
        uint32_t rA[4], rowB[4];
        #pragma unroll
        for (int mi = 0; mi < 4; mi++) rA[mi] = (wr * 64 + mi * 16 + lm) * 128;
        #pragma unroll
        for (int nb = 0; nb < 4; nb++) rowB[nb] = (wc * 64 + nb * 16 + co_off) * 128;

        uint32_t k0 = (wid & 1) << 1;
        int bs = 0; uint32_t bph = 0;
        for (int kh = 0; kh < 3; kh++) {
            uint32_t aph = kh & 1;
            for (int kw = 0; kw < 3; kw++) {
                uint32_t xw = xmk[kw];
                uint32_t kwoff = kw * 128;
                for (int kc = 0; kc < 4; kc++) {
                    if (kw == 0) mbar_wait(sb + SM_AFULL(kc), aph);
                    mbar_wait(sb + SM_BFULL(bs), bph);
                    uint32_t sa = sb + SM_ACH(kc) + kwoff;
                    uint32_t sbb = sb + SM_BST(bs);
                    #pragma unroll
                    for (int i = 0; i < 4; i++) {
                        uint32_t kb = ((i + k0) & 3) * 32;
                        uint32_t a[4][4], bf[4][4];
                        #pragma unroll
                        for (int mi = 0; mi < 4; mi++)
                            LDSM4(a[mi][0], a[mi][1], a[mi][2], a[mi][3],
                                  sa + rA[mi] + ((kb + kbA) ^ xw));
                        #pragma unroll
                        for (int nb = 0; nb < 4; nb++)
                            LDSM4(bf[nb][0], bf[nb][1], bf[nb][2], bf[nb][3],
                                  sbb + rowB[nb] + ((kb + kbB) ^ xmB));
                        if (i == 3 && lane == 0) {
                            mbar_arrive(sb + SM_BEMPTY(bs));
                            if (kw == 2) mbar_arrive(sb + SM_AEMPTY(kc));
                        }
                        #pragma unroll
                        for (int mi = 0; mi < 4; mi++)
                            #pragma unroll
                            for (int ni = 0; ni < 8; ni++)
                                mma16816(acc[mi][ni], a[mi], &bf[ni >> 1][(ni & 1) * 2]);
                    }
                    if (++bs == BSTAGES) { bs = 0; bph ^= 1; }
                }
            }
        }
    } else {
        // -------- producer warp (warp 4) --------
        if (elect_one()) {
            int bs = 0; uint32_t bph = 1;
            for (int kh = 0; kh < 3; kh++) {
                uint32_t aeph = (kh & 1) ^ 1;   // first wait passes on fresh barrier
                for (int kw = 0; kw < 3; kw++) {
                    for (int kc = 0; kc < 4; kc++) {
                        if (kw == 0) {
                            mbar_wait_relaxed(sb + SM_AEMPTY(kc), aeph);
                            mbar_expect_tx(sb + SM_AFULL(kc), A_TX);
                            tma2d(sb + SM_ACH(kc), &tmA, kc * 64,
                                  tile_base + kh * WP, sb + SM_AFULL(kc));
                        }
                        mbar_wait_relaxed(sb + SM_BEMPTY(bs), bph);
                        mbar_expect_tx(sb + SM_BFULL(bs), B_TX);
                        tma2d(sb + SM_BST(bs), &tmB, kc * 64,
                              (kh * 3 + kw) * 256 + co_base, sb + SM_BFULL(bs));
                        if (++bs == BSTAGES) { bs = 0; bph ^= 1; }
                    }
                }
            }
        }
    }

    // -------- epilogue: regs -> smem [co][m] -> coalesced NCHW --------
    __syncthreads();
    float* epi = reinterpret_cast<float*>(smem + SM_EPI);   // [128][stride 132]
    if (wid < 4) {
        int wr = wid >> 1, wc = wid & 1;
        int m0b = wr * 64 + (lane >> 2);
        int co0b = wc * 64 + (lane & 3) * 2;
        #pragma unroll
        for (int mi = 0; mi < 4; mi++)
            #pragma unroll
            for (int ni = 0; ni < 8; ni++) {
                int m0 = m0b + mi * 16;
                int co0 = co0b + ni * 8;
                epi[co0 * 132 + m0]           = acc[mi][ni][0];
                epi[(co0 + 1) * 132 + m0]     = acc[mi][ni][1];
                epi[co0 * 132 + m0 + 8]       = acc[mi][ni][2];
                epi[(co0 + 1) * 132 + m0 + 8] = acc[mi][ni][3];
            }
    }
    __syncthreads();
    if (tid < 128) {
        int m_l = tid;
        int m_g = tile_base + m_l;
        int n = m_g / IMG_ROWS;
        int rem = m_g - n * IMG_ROWS;
        int y = rem / WP, x = rem - y * WP;
        // Non-negative taps (kh*58+kw): GEMM row at padded (y,x) == output (y,x).
        bool valid = (y < HH) && (x < WW) && (n < NB);
        if (valid) {
            float* ob = out + (size_t)n * CIN * (HH * WW) + (size_t)y * WW + x;
            #pragma unroll 4
            for (int co = 0; co < 128; co++) {
                ob[(size_t)(co_base + co) * (HH * WW)] = epi[co * 132 + m_l] + sbias[co];
            }
        }
    }
}

// ---------------- host ----------------
typedef CUresult (*PFN_encodeTiled)(
    CUtensorMap*, CUtensorMapDataType, cuuint32_t, void*,
    const cuuint64_t*, const cuuint64_t*, const cuuint32_t*, const cuuint32_t*,
    CUtensorMapInterleave, CUtensorMapSwizzle, CUtensorMapL2promotion, CUtensorMapFloatOOBfill);

extern "C" void kernel_launch(void* const* d_in, const int* in_sizes, int n_in,
                              void* d_out, int out_size) {
    const float* x    = (const float*)d_in[0];
    const float* w    = (const float*)d_in[1];
    const float* bias = (const float*)d_in[2];
    float* out        = (float*)d_out;

    void* pA = nullptr; cudaGetSymbolAddress(&pA, g_a);
    void* pB = nullptr; cudaGetSymbolAddress(&pB, g_b);

    PFN_encodeTiled encode = nullptr;
    cudaDriverEntryPointQueryResult qr;
    cudaGetDriverEntryPointByVersion("cuTensorMapEncodeTiled", (void**)&encode, 12000,
                                     cudaEnableDefault, &qr);

    CUtensorMap tmA, tmB;
    {
        cuuint64_t dims[2]    = { 256, (cuuint64_t)R_TOTAL };
        cuuint64_t strides[1] = { 512 };
        cuuint32_t box[2]     = { 64u, 130u };                 // 128B x 130 rows (A chunk)
        cuuint32_t es[2]      = { 1u, 1u };
        encode(&tmA, CU_TENSOR_MAP_DATA_TYPE_FLOAT16, 2, pA, dims, strides, box, es,
               CU_TENSOR_MAP_INTERLEAVE_NONE, CU_TENSOR_MAP_SWIZZLE_128B,
               CU_TENSOR_MAP_L2_PROMOTION_L2_128B, CU_TENSOR_MAP_FLOAT_OOB_FILL_NONE);
    }
    {
        cuuint64_t dims[2]    = { 256, 9 * 256 };
        cuuint64_t strides[1] = { 512 };
        cuuint32_t box[2]     = { 64u, 128u };
        cuuint32_t es[2]      = { 1u, 1u };
        encode(&tmB, CU_TENSOR_MAP_DATA_TYPE_FLOAT16, 2, pB, dims, strides, box, es,
               CU_TENSOR_MAP_INTERLEAVE_NONE, CU_TENSOR_MAP_SWIZZLE_128B,
               CU_TENSOR_MAP_L2_PROMOTION_L2_128B, CU_TENSOR_MAP_FLOAT_OOB_FILL_NONE);
    }

    k_pre<<<FILL_BLKS + ZERO_BLKS + 256, 256>>>(x, w);

    cudaFuncSetAttribute(k_gemm, cudaFuncAttributeMaxDynamicSharedMemorySize, SMEM_BYTES);
    k_gemm<<<NTILES, 160, SMEM_BYTES>>>(tmA, tmB, bias, out);
}

// round 9
// speedup vs baseline: 1.1029x; 1.1029x over previous
#include <cuda_runtime.h>
#include <cuda.h>
#include <cuda_fp16.h>
#include <cstdint>

// ---------------- problem dims ----------------
#define NB 32
#define CIN 256
#define HH 56
#define WW 56
#define WP 58
#define IMG_ROWS (WP*WP)            // 3364
#define R_VALID (NB*IMG_ROWS)       // 107648 = 128*841
#define R_TOTAL 107904              // covers max tap offset (+118)
#define M_PER_CTA 128
#define N_PER_CTA 128
#define NTILES (841*2)              // 1682: (m-tile, n-half) pairs
#define ITERS 36                    // 9 taps * 4 k-chunks(64ch)
#define STAGES 3

// ---------------- smem layout ----------------
#define SM_FULL(s)  (16 + (s)*8)
#define SM_EMPTY(s) (64 + (s)*8)
#define SM_BIAS     1024
#define SM_STAGE(s) (2048 + (s)*32768)
#define SM_A(s) (SM_STAGE(s))
#define SM_B(s) (SM_STAGE(s) + 16384)
#define SM_EPI  2048
#define SMEM_BYTES (2048 + STAGES*32768)     // 100352 -> 2 CTAs/SM
#define STAGE_TX 32768u

// ---------------- device scratch ----------------
__device__ __align__(1024) __half g_a[(size_t)R_TOTAL * 256];     // 55.25 MB
__device__ __align__(1024) __half g_b[(size_t)9 * 256 * 256];     // 1.18 MB

// ---------------- PTX helpers (plain-sm_103-legal) ----------------
__device__ __forceinline__ uint32_t smem_u32(const void* p) {
    uint32_t a;
    asm("{ .reg .u64 t; cvta.to.shared.u64 t, %1; cvt.u32.u64 %0, t; }" : "=r"(a) : "l"(p));
    return a;
}
__device__ __forceinline__ bool elect_one() {
    uint32_t p;
    asm volatile("{ .reg .pred P; elect.sync _|P, 0xFFFFFFFF; selp.b32 %0, 1, 0, P; }" : "=r"(p));
    return p != 0;
}
__device__ __forceinline__ void mbar_init(uint32_t a, uint32_t cnt) {
    asm volatile("mbarrier.init.shared.b64 [%0], %1;" :: "r"(a), "r"(cnt) : "memory");
}
__device__ __forceinline__ void mbar_expect_tx(uint32_t a, uint32_t bytes) {
    asm volatile("mbarrier.arrive.expect_tx.shared.b64 _, [%0], %1;" :: "r"(a), "r"(bytes) : "memory");
}
__device__ __forceinline__ void mbar_arrive(uint32_t a) {
    asm volatile("mbarrier.arrive.shared.b64 _, [%0];" :: "r"(a) : "memory");
}
__device__ __forceinline__ void mbar_wait(uint32_t a, uint32_t phase) {
    asm volatile(
        "{\n\t.reg .pred P;\n\t"
        "W_%=:\n\t"
        "mbarrier.try_wait.parity.acquire.cta.shared::cta.b64 P, [%0], %1, 0x989680;\n\t"
        "@P bra.uni D_%=;\n\t"
        "bra.uni W_%=;\n\t"
        "D_%=:\n\t}"
        :: "r"(a), "r"(phase) : "memory");
}
__device__ __forceinline__ void mbar_wait_relaxed(uint32_t a, uint32_t phase) {
    asm volatile(
        "{\n\t.reg .pred P;\n\t"
        "W_%=:\n\t"
        "mbarrier.try_wait.parity.relaxed.cta.shared::cta.b64 P, [%0], %1, 0x989680;\n\t"
        "@P bra.uni D_%=;\n\t"
        "bra.uni W_%=;\n\t"
        "D_%=:\n\t}"
        :: "r"(a), "r"(phase) : "memory");
}
__device__ __forceinline__ void tma2d(uint32_t dst, const CUtensorMap* m, int cx, int cy, uint32_t mbar) {
    asm volatile(
        "cp.async.bulk.tensor.2d.shared::cta.global.tile.mbarrier::complete_tx::bytes "
        "[%0], [%1, {%2, %3}], [%4];"
        :: "r"(dst), "l"(m), "r"(cx), "r"(cy), "r"(mbar) : "memory");
}
#define LDSM4(r0,r1,r2,r3,addr) \
    asm volatile("ldmatrix.sync.aligned.m8n8.x4.shared.b16 {%0,%1,%2,%3}, [%4];" \
        : "=r"(r0), "=r"(r1), "=r"(r2), "=r"(r3) : "r"(addr))
__device__ __forceinline__ void mma16816(float* c, const uint32_t* a, const uint32_t* b) {
    asm volatile(
        "mma.sync.aligned.m16n8k16.row.col.f32.f16.f16.f32 "
        "{%0,%1,%2,%3}, {%4,%5,%6,%7}, {%8,%9}, {%0,%1,%2,%3};"
        : "+f"(c[0]), "+f"(c[1]), "+f"(c[2]), "+f"(c[3])
        : "r"(a[0]), "r"(a[1]), "r"(a[2]), "r"(a[3]), "r"(b[0]), "r"(b[1]));
}

// ---------------- merged pre-pass: fill + border-zero + wprep ----------------
// blocks [0,7168): NCHW fp32 -> padded fp16 transpose
// blocks [7168,8112): zero border/tail rows
// blocks [8112,8368): sign(w) -> fp16 B[tap][co][ci]
#define FILL_BLKS (56*4*32)        // 7168
#define ZERO_BLKS 944
__global__ void k_pre(const float* __restrict__ x, const float* __restrict__ w) {
    __shared__ float s[64][57];
    int b = blockIdx.x;
    if (b < FILL_BLKS) {
        int n = b / 224, r = b % 224, cb = r / 56, h = r % 56;
        int ci0 = cb * 64;
        for (int idx = threadIdx.x; idx < 64 * 14; idx += blockDim.x) {
            int cl = idx / 14, q = idx % 14;
            float4 v = reinterpret_cast<const float4*>(
                x + (((size_t)n * CIN + ci0 + cl) * HH + h) * WW)[q];
            s[cl][q * 4 + 0] = v.x; s[cl][q * 4 + 1] = v.y;
            s[cl][q * 4 + 2] = v.z; s[cl][q * 4 + 3] = v.w;
        }
        __syncthreads();
        for (int idx = threadIdx.x; idx < WW * 32; idx += blockDim.x) {
            int ww = idx >> 5, p = idx & 31;
            __half2 hv = __floats2half2_rn(s[p * 2][ww], s[p * 2 + 1][ww]);
            size_t row = (size_t)n * IMG_ROWS + (size_t)(h + 1) * WP + (ww + 1);
            reinterpret_cast<__half2*>(g_a + row * 256 + ci0)[p] = hv;
        }
    } else if (b < FILL_BLKS + ZERO_BLKS) {
        int r = (b - FILL_BLKS) * 8 + (threadIdx.x >> 5);
        int lane = threadIdx.x & 31;
        size_t row;
        if (r < 32 * 228) {
            int n = r / 228, bb = r - n * 228;
            int y, xx;
            if (bb < 58)       { y = 0;  xx = bb; }
            else if (bb < 116) { y = 57; xx = bb - 58; }
            else if (bb < 172) { y = bb - 116 + 1; xx = 0; }
            else               { y = bb - 172 + 1; xx = 57; }
            row = (size_t)n * IMG_ROWS + (size_t)y * WP + xx;
        } else {
            row = (size_t)R_VALID + (r - 32 * 228);
        }
        uint4 z = make_uint4(0u, 0u, 0u, 0u);
        reinterpret_cast<uint4*>(g_a + row * 256)[lane] = z;
    } else {
        int t = (b - FILL_BLKS - ZERO_BLKS) * 256 + threadIdx.x;
        int co = t >> 8, ci = t & 255;
        const float* wp = w + (size_t)(co * 256 + ci) * 9;
        #pragma unroll
        for (int tap = 0; tap < 9; tap++) {
            float v = wp[tap];
            float sgn = (v > 0.f) ? 1.f : ((v < 0.f) ? -1.f : 0.f);
            g_b[((size_t)tap * 256 + co) * 256 + ci] = __float2half_rn(sgn);
        }
    }
}

// ---------------- main GEMM kernel: 128m x 128n per CTA, 2 CTAs/SM ----------------
__global__ void __launch_bounds__(160, 2) k_gemm(
    const __grid_constant__ CUtensorMap tmA,
    const __grid_constant__ CUtensorMap tmB,
    const float* __restrict__ bias,
    float* __restrict__ out)
{
    extern __shared__ __align__(1024) char smem[];
    uint32_t sb = smem_u32(smem);
    int tid = threadIdx.x, wid = tid >> 5, lane = tid & 31;

    if (tid == 0) {
        for (int s = 0; s < STAGES; s++) {
            mbar_init(sb + SM_FULL(s), 1);
            mbar_init(sb + SM_EMPTY(s), 4);   // 4 consumer warps
        }
    }
    int mt  = blockIdx.x >> 1;          // m-tile (adjacent CTAs share A tile)
    int nco = blockIdx.x & 1;           // n-half
    int tile_base = mt * M_PER_CTA;
    int co_base = nco * N_PER_CTA;

    float* sbias = reinterpret_cast<float*>(smem + SM_BIAS);
    if (tid < 128) sbias[tid] = bias[co_base + tid];
    __syncthreads();

    float acc[4][8][4];
    #pragma unroll
    for (int mi = 0; mi < 4; mi++)
        #pragma unroll
        for (int ni = 0; ni < 8; ni++)
            #pragma unroll
            for (int r = 0; r < 4; r++) acc[mi][ni][r] = 0.f;

    if (wid < 4) {
        // -------- compute warps: 2x2 grid, 64x64 warp tile --------
        int wr = wid >> 1, wc = wid & 1;
        uint32_t lm = lane & 15;
        uint32_t kbA = (lane >> 4) * 16;                               // A: k-halves
        uint32_t co_off = (lane & 7) + ((lane >> 4) & 1) * 8;          // B: co within 16
        uint32_t kbB = ((lane >> 3) & 1) * 16;                         // B: k-halves
        uint32_t xm = (lane & 7) << 4;                                 // SW128 xor
        uint32_t rowA[4], rowB[4];
        #pragma unroll
        for (int mi = 0; mi < 4; mi++) rowA[mi] = (wr * 64 + mi * 16 + lm) * 128;
        #pragma unroll
        for (int nb = 0; nb < 4; nb++) rowB[nb] = (wc * 64 + nb * 16 + co_off) * 128;

        uint32_t k0 = (wid & 1) << 1;   // stagger k-step order between warps
        int s = 0; uint32_t ph = 0;
        for (int it = 0; it < ITERS; it++) {
            mbar_wait(sb + SM_FULL(s), ph);
            uint32_t sa = sb + SM_A(s), sbb = sb + SM_B(s);
            #pragma unroll
            for (int i = 0; i < 4; i++) {
                uint32_t kb = ((i + k0) & 3) * 32;
                uint32_t a[4][4], bf[4][4];
                #pragma unroll
                for (int mi = 0; mi < 4; mi++)
                    LDSM4(a[mi][0], a[mi][1], a[mi][2], a[mi][3],
                          sa + rowA[mi] + ((kb + kbA) ^ xm));
                #pragma unroll
                for (int nb = 0; nb < 4; nb++)
                    LDSM4(bf[nb][0], bf[nb][1], bf[nb][2], bf[nb][3],
                          sbb + rowB[nb] + ((kb + kbB) ^ xm));
                // After this warp's LAST ldmatrix of the stage, release to TMA.
                if (i == 3 && lane == 0) mbar_arrive(sb + SM_EMPTY(s));
                #pragma unroll
                for (int mi = 0; mi < 4; mi++)
                    #pragma unroll
                    for (int ni = 0; ni < 8; ni++)
                        mma16816(acc[mi][ni], a[mi], &bf[ni >> 1][(ni & 1) * 2]);
            }
            if (++s == STAGES) { s = 0; ph ^= 1; }
        }
    } else {
        // -------- producer warp (warp 4) --------
        if (elect_one()) {
            int s = 0; uint32_t ph = 1;
            for (int it = 0; it < ITERS; it++) {
                int tap = it >> 2, kc = it & 3;
                int off = (tap / 3) * WP + (tap % 3);   // kh*58 + kw
                mbar_wait_relaxed(sb + SM_EMPTY(s), ph);
                mbar_expect_tx(sb + SM_FULL(s), STAGE_TX);
                tma2d(sb + SM_A(s), &tmA, kc * 64, tile_base + off,        sb + SM_FULL(s));
                tma2d(sb + SM_B(s), &tmB, kc * 64, tap * 256 + co_base,    sb + SM_FULL(s));
                if (++s == STAGES) { s = 0; ph ^= 1; }
            }
        }
    }

    // -------- epilogue: regs -> smem [co][m] -> coalesced NCHW --------
    __syncthreads();
    float* epi = reinterpret_cast<float*>(smem + SM_EPI);   // [128][stride 132]
    if (wid < 4) {
        int wr = wid >> 1, wc = wid & 1;
        int m0b = wr * 64 + (lane >> 2);
        int co0b = wc * 64 + (lane & 3) * 2;
        #pragma unroll
        for (int mi = 0; mi < 4; mi++)
            #pragma unroll
            for (int ni = 0; ni < 8; ni++) {
                int m0 = m0b + mi * 16;
                int co0 = co0b + ni * 8;
                epi[co0 * 132 + m0]           = acc[mi][ni][0];
                epi[(co0 + 1) * 132 + m0]     = acc[mi][ni][1];
                epi[co0 * 132 + m0 + 8]       = acc[mi][ni][2];
                epi[(co0 + 1) * 132 + m0 + 8] = acc[mi][ni][3];
            }
    }
    __syncthreads();
    if (tid < 128) {
        int m_l = tid;
        int m_g = tile_base + m_l;
        int n = m_g / IMG_ROWS;
        int rem = m_g - n * IMG_ROWS;
        int y = rem / WP, x = rem - y * WP;
        // Non-negative taps (kh*58+kw): GEMM row at padded (y,x) == output (y,x).
        bool valid = (y < HH) && (x < WW) && (n < NB);
        if (valid) {
            float* ob = out + (size_t)n * CIN * (HH * WW) + (size_t)y * WW + x;
            #pragma unroll 8
            for (int co = 0; co < 128; co++) {
                ob[(size_t)(co_base + co) * (HH * WW)] = epi[co * 132 + m_l] + sbias[co];
            }
        }
    }
}

// ---------------- host ----------------
typedef CUresult (*PFN_encodeTiled)(
    CUtensorMap*, CUtensorMapDataType, cuuint32_t, void*,
    const cuuint64_t*, const cuuint64_t*, const cuuint32_t*, const cuuint32_t*,
    CUtensorMapInterleave, CUtensorMapSwizzle, CUtensorMapL2promotion, CUtensorMapFloatOOBfill);

extern "C" void kernel_launch(void* const* d_in, const int* in_sizes, int n_in,
                              void* d_out, int out_size) {
    const float* x    = (const float*)d_in[0];
    const float* w    = (const float*)d_in[1];
    const float* bias = (const float*)d_in[2];
    float* out        = (float*)d_out;

    void* pA = nullptr; cudaGetSymbolAddress(&pA, g_a);
    void* pB = nullptr; cudaGetSymbolAddress(&pB, g_b);

    PFN_encodeTiled encode = nullptr;
    cudaDriverEntryPointQueryResult qr;
    cudaGetDriverEntryPointByVersion("cuTensorMapEncodeTiled", (void**)&encode, 12000,
                                     cudaEnableDefault, &qr);

    CUtensorMap tmA, tmB;
    {
        cuuint64_t dims[2]    = { 256, (cuuint64_t)R_TOTAL };
        cuuint64_t strides[1] = { 512 };                       // 256 fp16 = 512 B
        cuuint32_t box[2]     = { 64u, 128u };                 // 128B x 128 rows
        cuuint32_t es[2]      = { 1u, 1u };
        encode(&tmA, CU_TENSOR_MAP_DATA_TYPE_FLOAT16, 2, pA, dims, strides, box, es,
               CU_TENSOR_MAP_INTERLEAVE_NONE, CU_TENSOR_MAP_SWIZZLE_128B,
               CU_TENSOR_MAP_L2_PROMOTION_L2_128B, CU_TENSOR_MAP_FLOAT_OOB_FILL_NONE);
    }
    {
        cuuint64_t dims[2]    = { 256, 9 * 256 };
        cuuint64_t strides[1] = { 512 };
        cuuint32_t box[2]     = { 64u, 128u };                 // 128B x 128 co rows
        cuuint32_t es[2]      = { 1u, 1u };
        encode(&tmB, CU_TENSOR_MAP_DATA_TYPE_FLOAT16, 2, pB, dims, strides, box, es,
               CU_TENSOR_MAP_INTERLEAVE_NONE, CU_TENSOR_MAP_SWIZZLE_128B,
               CU_TENSOR_MAP_L2_PROMOTION_L2_128B, CU_TENSOR_MAP_FLOAT_OOB_FILL_NONE);
    }

    k_pre<<<FILL_BLKS + ZERO_BLKS + 256, 256>>>(x, w);

    cudaFuncSetAttribute(k_gemm, cudaFuncAttributeMaxDynamicSharedMemorySize, SMEM_BYTES);
    k_gemm<<<NTILES, 160, SMEM_BYTES>>>(tmA, tmB, bias, out);
}